// round 8
// baseline (speedup 1.0000x reference)
#include <cuda_runtime.h>
#include <math.h>

#define BB 2
#define SS 2048
#define DIMD 512
#define HEADS 4
#define DH 128
#define CHUNK 16
#define NCHUNK 128
#define BH 8
#define DH2 16384
#define MAX_LR 0.01f
#define EPSV 1e-6f

// ---------------- scratch ----------------
__device__ float g_xnorm[BB*SS*DIMD];
__device__ float g_k[BH*NCHUNK*CHUNK*DH];
__device__ float g_v[BH*NCHUNK*CHUNK*DH];
__device__ float g_a[BH*NCHUNK*CHUNK*DH];    // silu(h)
__device__ float g_gn[BH*NCHUNK*CHUNK*DH];   // Gn = f*(v - pred)
__device__ float g_dh[BH*NCHUNK*CHUNK*DH];   // dh
__device__ float g_lr[BH*NCHUNK*CHUNK];
__device__ float g_mom[BH*NCHUNK];
__device__ float g_dec[BH*NCHUNK];

__device__ __forceinline__ float sigf(float x) { return 1.f / (1.f + __expf(-x)); }

// ------- packed f32x2 helpers -------
__device__ __forceinline__ unsigned long long fma2(unsigned long long a,
                                                   unsigned long long b,
                                                   unsigned long long c) {
    unsigned long long d;
    asm("fma.rn.f32x2 %0, %1, %2, %3;" : "=l"(d) : "l"(a), "l"(b), "l"(c));
    return d;
}
__device__ __forceinline__ unsigned long long dup2(float x) {
    unsigned long long d;
    unsigned int xi = __float_as_uint(x);
    asm("mov.b64 %0, {%1, %1};" : "=l"(d) : "r"(xi));
    return d;
}
__device__ __forceinline__ float2 unpk2(unsigned long long v) {
    unsigned int lo, hi;
    asm("mov.b64 {%0, %1}, %2;" : "=r"(lo), "=r"(hi) : "l"(v));
    return make_float2(__uint_as_float(lo), __uint_as_float(hi));
}

// ---------------- K1: RMSNorm + per-token lr ----------------
__global__ void k_rmsnorm(const float* __restrict__ seq,
                          const float* __restrict__ scale,
                          const float* __restrict__ Wstep) {
    int tok = blockIdx.x;
    int tid = threadIdx.x;
    int lane = tid & 31, warp = tid >> 5;
    __shared__ float red[4];
    __shared__ float redp[4][4];

    float4 v = ((const float4*)(seq + (size_t)tok * DIMD))[tid];
    float ss = v.x*v.x + v.y*v.y + v.z*v.z + v.w*v.w;
#pragma unroll
    for (int o = 16; o; o >>= 1) ss += __shfl_xor_sync(0xffffffffu, ss, o);
    if (lane == 0) red[warp] = ss;
    __syncthreads();
    float tot = red[0] + red[1] + red[2] + red[3];
    float inv = rsqrtf(tot * (1.f / DIMD) + EPSV);

    float4 sc = ((const float4*)scale)[tid];
    float4 xn = make_float4(v.x*inv*sc.x, v.y*inv*sc.y, v.z*inv*sc.z, v.w*inv*sc.w);
    ((float4*)(g_xnorm + (size_t)tok * DIMD))[tid] = xn;

    int d0 = tid * 4;
    float4 wa = ((const float4*)Wstep)[d0 + 0];
    float4 wb = ((const float4*)Wstep)[d0 + 1];
    float4 wc = ((const float4*)Wstep)[d0 + 2];
    float4 wd = ((const float4*)Wstep)[d0 + 3];
    float p0 = xn.x*wa.x + xn.y*wb.x + xn.z*wc.x + xn.w*wd.x;
    float p1 = xn.x*wa.y + xn.y*wb.y + xn.z*wc.y + xn.w*wd.y;
    float p2 = xn.x*wa.z + xn.y*wb.z + xn.z*wc.z + xn.w*wd.z;
    float p3 = xn.x*wa.w + xn.y*wb.w + xn.z*wc.w + xn.w*wd.w;
#pragma unroll
    for (int o = 16; o; o >>= 1) {
        p0 += __shfl_xor_sync(0xffffffffu, p0, o);
        p1 += __shfl_xor_sync(0xffffffffu, p1, o);
        p2 += __shfl_xor_sync(0xffffffffu, p2, o);
        p3 += __shfl_xor_sync(0xffffffffu, p3, o);
    }
    if (lane == 0) { redp[warp][0] = p0; redp[warp][1] = p1; redp[warp][2] = p2; redp[warp][3] = p3; }
    __syncthreads();
    if (tid < 4) {
        float p = redp[0][tid] + redp[1][tid] + redp[2][tid] + redp[3][tid];
        float lrv = MAX_LR * sigf(p);
        int b = tok / SS, s = tok % SS;
        int t = s / CHUNK, c = s % CHUNK;
        g_lr[(((b * HEADS + tid) * NCHUNK + t) * CHUNK) + c] = lrv;
    }
}

// ---------------- K2: chunk means -> mom/dec ----------------
__global__ void k_chunkstats(const float* __restrict__ Wmom,
                             const float* __restrict__ Wdec) {
    int blk = blockIdx.x;
    int b = blk / NCHUNK, t = blk % NCHUNK;
    int tid = threadIdx.x;
    int lane = tid & 31, warp = tid >> 5;
    __shared__ float redp[4][8];

    int d0 = tid * 4;
    const float* xb = g_xnorm + ((size_t)(b * SS + t * CHUNK)) * DIMD;
    float4 m = make_float4(0.f, 0.f, 0.f, 0.f);
#pragma unroll
    for (int c = 0; c < CHUNK; c++) {
        float4 v = *(const float4*)(xb + (size_t)c * DIMD + d0);
        m.x += v.x; m.y += v.y; m.z += v.z; m.w += v.w;
    }
    m.x *= (1.f/CHUNK); m.y *= (1.f/CHUNK); m.z *= (1.f/CHUNK); m.w *= (1.f/CHUNK);

    float4 ma = ((const float4*)Wmom)[d0 + 0];
    float4 mb = ((const float4*)Wmom)[d0 + 1];
    float4 mc = ((const float4*)Wmom)[d0 + 2];
    float4 md = ((const float4*)Wmom)[d0 + 3];
    float4 da = ((const float4*)Wdec)[d0 + 0];
    float4 db = ((const float4*)Wdec)[d0 + 1];
    float4 dc = ((const float4*)Wdec)[d0 + 2];
    float4 dd = ((const float4*)Wdec)[d0 + 3];

    float p[8];
    p[0] = m.x*ma.x + m.y*mb.x + m.z*mc.x + m.w*md.x;
    p[1] = m.x*ma.y + m.y*mb.y + m.z*mc.y + m.w*md.y;
    p[2] = m.x*ma.z + m.y*mb.z + m.z*mc.z + m.w*md.z;
    p[3] = m.x*ma.w + m.y*mb.w + m.z*mc.w + m.w*md.w;
    p[4] = m.x*da.x + m.y*db.x + m.z*dc.x + m.w*dd.x;
    p[5] = m.x*da.y + m.y*db.y + m.z*dc.y + m.w*dd.y;
    p[6] = m.x*da.z + m.y*db.z + m.z*dc.z + m.w*dd.z;
    p[7] = m.x*da.w + m.y*db.w + m.z*dc.w + m.w*dd.w;
#pragma unroll
    for (int i = 0; i < 8; i++) {
#pragma unroll
        for (int o = 16; o; o >>= 1) p[i] += __shfl_xor_sync(0xffffffffu, p[i], o);
    }
    if (lane == 0) {
#pragma unroll
        for (int i = 0; i < 8; i++) redp[warp][i] = p[i];
    }
    __syncthreads();
    if (tid < 8) {
        float s = redp[0][tid] + redp[1][tid] + redp[2][tid] + redp[3][tid];
        float sv = sigf(s);
        int h = tid & 3;
        if (tid < 4) g_mom[(b * HEADS + h) * NCHUNK + t] = sv;
        else         g_dec[(b * HEADS + h) * NCHUNK + t] = sv;
    }
}

// ---------------- K3: kv projection (32-token tiles) ----------------
#define KV_ROWS 32
__global__ void __launch_bounds__(256, 2) k_kvproj(const float* __restrict__ Wkv) {
    extern __shared__ float xs[];   // 64 KB
    int rg  = blockIdx.x & 127;
    int cgp = blockIdx.x >> 7;
    int tid = threadIdx.x;

    const float4* src = (const float4*)(g_xnorm + (size_t)rg * KV_ROWS * DIMD);
#pragma unroll
    for (int i = tid; i < KV_ROWS * DIMD / 4; i += 256) ((float4*)xs)[i] = src[i];
    __syncthreads();

    int rs = tid >> 6;
    int cg = tid & 63;
    int r0 = rs * 8;
    int col = cgp * 256 + cg * 4;

    unsigned long long acc[8][2];
#pragma unroll
    for (int r = 0; r < 8; r++) { acc[r][0] = 0ull; acc[r][1] = 0ull; }

    const float* wbase = Wkv + col;
#pragma unroll 2
    for (int dt = 0; dt < DIMD; dt += 4) {
        float4 xv[8];
#pragma unroll
        for (int r = 0; r < 8; r++) xv[r] = *(const float4*)&xs[(r0 + r) * DIMD + dt];
#pragma unroll
        for (int dd = 0; dd < 4; dd++) {
            ulonglong2 wl = *(const ulonglong2*)(wbase + (size_t)(dt + dd) * 1024);
#pragma unroll
            for (int r = 0; r < 8; r++) {
                float xc = (dd == 0) ? xv[r].x : (dd == 1) ? xv[r].y : (dd == 2) ? xv[r].z : xv[r].w;
                unsigned long long kk = dup2(xc);
                acc[r][0] = fma2(kk, wl.x, acc[r][0]);
                acc[r][1] = fma2(kk, wl.y, acc[r][1]);
            }
        }
    }

    int isv = (col >= 512);
    int c2 = col - isv * 512;
    int h = c2 >> 7, j = c2 & 127;
    float* base = (isv ? g_v : g_k);
#pragma unroll
    for (int r = 0; r < 8; r++) {
        int tg = rg * KV_ROWS + r0 + r;
        int b = tg >> 11, s = tg & 2047;
        float* dst = base + ((size_t)((b * HEADS + h) * SS + s)) * DH + j;
        *(ulonglong2*)dst = make_ulonglong2(acc[r][0], acc[r][1]);
    }
}

// ---------------- K4a: per-chunk gradients (512 thr, 4x4 tiles) ----------------
#define CPG 4
#define MROWS 64
#define WPITCH 140

__device__ __forceinline__ void gemm64(const float* __restrict__ A,
                                       const float* __restrict__ W,
                                       int c0, int j0,
                                       unsigned long long acc[4][2]) {
#pragma unroll
    for (int i = 0; i < 4; i++) { acc[i][0] = 0ull; acc[i][1] = 0ull; }
#pragma unroll 2
    for (int dq = 0; dq < DH; dq += 4) {
        float4 ar[4];
#pragma unroll
        for (int i = 0; i < 4; i++) ar[i] = *(const float4*)&A[(c0 + i) * DH + dq];
#pragma unroll
        for (int dd = 0; dd < 4; dd++) {
            ulonglong2 w = *(const ulonglong2*)&W[(dq + dd) * WPITCH + j0];
#pragma unroll
            for (int i = 0; i < 4; i++) {
                float av = (dd == 0) ? ar[i].x : (dd == 1) ? ar[i].y : (dd == 2) ? ar[i].z : ar[i].w;
                unsigned long long aa = dup2(av);
                acc[i][0] = fma2(aa, w.x, acc[i][0]);
                acc[i][1] = fma2(aa, w.y, acc[i][1]);
            }
        }
    }
}

__global__ void __launch_bounds__(512, 1)
k_grad(const float* __restrict__ w0g_all, const float* __restrict__ w1g_all) {
    extern __shared__ float sm[];
    float* ws  = sm;
    float* ks  = ws + 128 * WPITCH;
    float* vs  = ks + MROWS * DH;
    float* as_ = vs + MROWS * DH;
    float* ss  = as_ + MROWS * DH;
    float* lrs = ss + MROWS * DH;

    int bh = blockIdx.x >> 5;
    int tg = blockIdx.x & 31;
    int t0 = tg * CPG;
    int tid = threadIdx.x;

    size_t rowbase = ((size_t)(bh * NCHUNK + t0)) * (CHUNK * DH);

    const float4* kg = (const float4*)(g_k + rowbase);
    const float4* vg = (const float4*)(g_v + rowbase);
    for (int i = tid; i < MROWS * DH / 4; i += 512) {
        ((float4*)ks)[i] = kg[i];
        ((float4*)vs)[i] = vg[i];
    }
    if (tid < MROWS) lrs[tid] = g_lr[(bh * NCHUNK + t0) * CHUNK + tid];
    const float4* w0g4 = (const float4*)(w0g_all + (size_t)bh * DH2);
    for (int i = tid; i < 4096; i += 512) {
        int row = i >> 5, col = (i & 31) * 4;
        *(float4*)&ws[row * WPITCH + col] = w0g4[i];
    }
    __syncthreads();

    int ty = tid >> 5, tx = tid & 31;
    int c0 = ty * 4, j0 = tx * 4;
    unsigned long long acc[4][2];

    // GEMM A
    gemm64(ks, ws, c0, j0, acc);
#pragma unroll
    for (int i = 0; i < 4; i++) {
        float2 h01 = unpk2(acc[i][0]), h23 = unpk2(acc[i][1]);
        float s0 = sigf(h01.x), s1 = sigf(h01.y), s2 = sigf(h23.x), s3 = sigf(h23.y);
        float4 av = make_float4(h01.x * s0, h01.y * s1, h23.x * s2, h23.y * s3);
        *(float4*)&ss[(c0 + i) * DH + j0]  = make_float4(s0, s1, s2, s3);
        *(float4*)&as_[(c0 + i) * DH + j0] = av;
        *(float4*)&g_a[rowbase + (size_t)(c0 + i) * DH + j0] = av;
    }
    __syncthreads();

    const float4* w1g4 = (const float4*)(w1g_all + (size_t)bh * DH2);
    for (int i = tid; i < 4096; i += 512) {
        int row = i >> 5, col = (i & 31) * 4;
        *(float4*)&ws[row * WPITCH + col] = w1g4[i];
    }
    __syncthreads();

    // GEMM B
    gemm64(as_, ws, c0, j0, acc);
#pragma unroll
    for (int i = 0; i < 4; i++) {
        float f = 2.f * lrs[c0 + i] * (1.f / DH);
        float2 p01 = unpk2(acc[i][0]), p23 = unpk2(acc[i][1]);
        float4 vv = *(const float4*)&vs[(c0 + i) * DH + j0];
        float4 Gn = make_float4(f * (vv.x - p01.x), f * (vv.y - p01.y),
                                f * (vv.z - p23.x), f * (vv.w - p23.y));
        *(float4*)&vs[(c0 + i) * DH + j0] = Gn;
        *(float4*)&g_gn[rowbase + (size_t)(c0 + i) * DH + j0] = Gn;
    }
    __syncthreads();

    {
        const float* w1g = w1g_all + (size_t)bh * DH2;
        for (int i = tid; i < DH2; i += 512) {
            ws[(i & 127) * WPITCH + (i >> 7)] = w1g[i];
        }
    }
    __syncthreads();

    // GEMM C
    gemm64(vs, ws, c0, j0, acc);
#pragma unroll
    for (int i = 0; i < 4; i++) {
        float2 d01 = unpk2(acc[i][0]), d23 = unpk2(acc[i][1]);
        float4 sv = *(const float4*)&ss[(c0 + i) * DH + j0];
        float4 av = *(const float4*)&as_[(c0 + i) * DH + j0];
        d01.x *= sv.x + av.x * (1.f - sv.x);
        d01.y *= sv.y + av.y * (1.f - sv.y);
        d23.x *= sv.z + av.z * (1.f - sv.z);
        d23.y *= sv.w + av.w * (1.f - sv.w);
        *(float4*)&g_dh[rowbase + (size_t)(c0 + i) * DH + j0] =
            make_float4(d01.x, d01.y, d23.x, d23.y);
    }
}

// ---------------- K4b: fused outer-product + momentum/decay scan ----------------
// grid 128: cid = blk>>3 (sel*8+bh), tile = blk&7. block 256 (8 warps).
// Pipeline per t: LDG(t+1)->regs ; compute(t) from smem ; scan+store ; STS(regs->buf^1) ; sync.
#define SC_D1 32
#define SC_D2 64
__global__ void __launch_bounds__(256, 1) k_outer_scan(float* __restrict__ out) {
    __shared__ float As[2][CHUNK * SC_D1];
    __shared__ float Gs[2][CHUNK * SC_D2];
    __shared__ float moms[NCHUNK], decs[NCHUNK];

    int cid  = blockIdx.x >> 3;
    int sel  = cid >> 3, bh = cid & 7;
    int tile = blockIdx.x & 7;
    int d1b  = (tile >> 1) * SC_D1;
    int d2b  = (tile & 1) * SC_D2;
    int tid  = threadIdx.x;
    int w = tid >> 5, l = tid & 31;

    if (tid < NCHUNK) {
        moms[tid] = g_mom[bh * NCHUNK + tid];
        decs[tid] = 1.f - g_dec[bh * NCHUNK + tid];
    }

    const float* Asrc = sel ? g_a  : g_k;
    const float* Gsrc = sel ? g_gn : g_dh;
    size_t bhrow = (size_t)bh * (NCHUNK * CHUNK);

    // loaders: A 16x32 = 128 float4 (tid<128); G 16x64 = 256 float4 (all)
    int a_c = tid >> 3, a_i = (tid & 7) * 4;
    int g_c = tid >> 4, g_i = (tid & 15) * 4;

    // prologue: stage t=0
    if (tid < 128) {
        const float* ap = Asrc + (bhrow + a_c) * DH + d1b + a_i;
        *(float4*)&As[0][a_c * SC_D1 + a_i] = *(const float4*)ap;
    }
    {
        const float* gp = Gsrc + (bhrow + g_c) * DH + d2b + g_i;
        *(float4*)&Gs[0][g_c * SC_D2 + g_i] = *(const float4*)gp;
    }
    __syncthreads();

    unsigned long long m[4], u[4];
#pragma unroll
    for (int r = 0; r < 4; r++) { m[r] = 0ull; u[r] = 0ull; }

    size_t outchain = (size_t)(sel * BH + bh) * NCHUNK;
    int r0 = w * 4;   // warp's 4 rows within the 32-row tile

    for (int t = 0; t < NCHUNK; t++) {
        int cur = t & 1;
        bool havenext = (t + 1 < NCHUNK);
        float4 ar, gr;
        if (havenext) {
            if (tid < 128)
                ar = *(const float4*)(Asrc + (bhrow + (size_t)(t + 1) * CHUNK + a_c) * DH + d1b + a_i);
            gr = *(const float4*)(Gsrc + (bhrow + (size_t)(t + 1) * CHUNK + g_c) * DH + d2b + g_i);
        }

        // compute 4x2 outer tile from current buffers
        unsigned long long acc[4];
#pragma unroll
        for (int r = 0; r < 4; r++) acc[r] = 0ull;
#pragma unroll
        for (int c = 0; c < CHUNK; c++) {
            float4 av = *(const float4*)&As[cur][c * SC_D1 + r0];
            unsigned long long g2 = *(const unsigned long long*)&Gs[cur][c * SC_D2 + l * 2];
            acc[0] = fma2(dup2(av.x), g2, acc[0]);
            acc[1] = fma2(dup2(av.y), g2, acc[1]);
            acc[2] = fma2(dup2(av.z), g2, acc[2]);
            acc[3] = fma2(dup2(av.w), g2, acc[3]);
        }

        // scan update + store
        unsigned long long mo = dup2(moms[t]);
        unsigned long long de = dup2(decs[t]);
        float* op = out + (outchain + t) * DH2 + (size_t)(d1b + r0) * DH + d2b + l * 2;
#pragma unroll
        for (int r = 0; r < 4; r++) {
            m[r] = fma2(mo, m[r], acc[r]);
            u[r] = fma2(de, u[r], m[r]);
            *(unsigned long long*)(op + (size_t)r * DH) = u[r];
        }

        // stage next into the other buffer
        if (havenext) {
            if (tid < 128)
                *(float4*)&As[cur ^ 1][a_c * SC_D1 + a_i] = ar;
            *(float4*)&Gs[cur ^ 1][g_c * SC_D2 + g_i] = gr;
        }
        __syncthreads();
    }
}

// ---------------- launch ----------------
extern "C" void kernel_launch(void* const* d_in, const int* in_sizes, int n_in,
                              void* d_out, int out_size) {
    const float* seq   = (const float*)d_in[0];
    const float* scale = (const float*)d_in[1];
    const float* Wkv   = (const float*)d_in[2];
    const float* Wstep = (const float*)d_in[3];
    const float* Wmom  = (const float*)d_in[4];
    const float* Wdec  = (const float*)d_in[5];
    const float* w0    = (const float*)d_in[6];
    const float* w1    = (const float*)d_in[7];
    float* out = (float*)d_out;

    const int GRAD_SMEM = (128 * WPITCH + 4 * MROWS * DH + 64) * 4;  // ~203 KB
    const int KV_SMEM = KV_ROWS * DIMD * 4;                           // 64 KB
    cudaFuncSetAttribute(k_grad, cudaFuncAttributeMaxDynamicSharedMemorySize, GRAD_SMEM);
    cudaFuncSetAttribute(k_kvproj, cudaFuncAttributeMaxDynamicSharedMemorySize, KV_SMEM);

    k_rmsnorm<<<BB * SS, 128>>>(seq, scale, Wstep);
    k_chunkstats<<<BB * NCHUNK, 128>>>(Wmom, Wdec);
    k_kvproj<<<512, 256, KV_SMEM>>>(Wkv);
    k_grad<<<BH * (NCHUNK / CPG), 512, GRAD_SMEM>>>(w0, w1);
    k_outer_scan<<<128, 256>>>(out);
}

// round 9
// speedup vs baseline: 1.2819x; 1.2819x over previous
#include <cuda_runtime.h>
#include <math.h>

#define BB 2
#define SS 2048
#define DIMD 512
#define HEADS 4
#define DH 128
#define CHUNK 16
#define NCHUNK 128
#define BH 8
#define DH2 16384
#define MAX_LR 0.01f
#define EPSV 1e-6f

// ---------------- scratch ----------------
__device__ float g_xnorm[BB*SS*DIMD];
__device__ float g_k[BH*NCHUNK*CHUNK*DH];
__device__ float g_v[BH*NCHUNK*CHUNK*DH];
__device__ float g_a[BH*NCHUNK*CHUNK*DH];    // silu(h)
__device__ float g_gn[BH*NCHUNK*CHUNK*DH];   // Gn = f*(v - pred)
__device__ float g_dh[BH*NCHUNK*CHUNK*DH];   // dh
__device__ float g_lr[BH*NCHUNK*CHUNK];
__device__ float g_mom[BH*NCHUNK];
__device__ float g_dec[BH*NCHUNK];

__device__ __forceinline__ float sigf(float x) { return 1.f / (1.f + __expf(-x)); }

// ------- packed f32x2 helpers -------
__device__ __forceinline__ unsigned long long fma2(unsigned long long a,
                                                   unsigned long long b,
                                                   unsigned long long c) {
    unsigned long long d;
    asm("fma.rn.f32x2 %0, %1, %2, %3;" : "=l"(d) : "l"(a), "l"(b), "l"(c));
    return d;
}
__device__ __forceinline__ unsigned long long dup2(float x) {
    unsigned long long d;
    unsigned int xi = __float_as_uint(x);
    asm("mov.b64 %0, {%1, %1};" : "=l"(d) : "r"(xi));
    return d;
}
__device__ __forceinline__ float2 unpk2(unsigned long long v) {
    unsigned int lo, hi;
    asm("mov.b64 {%0, %1}, %2;" : "=r"(lo), "=r"(hi) : "l"(v));
    return make_float2(__uint_as_float(lo), __uint_as_float(hi));
}
__device__ __forceinline__ void st_cs_u64(float* p, unsigned long long v) {
    asm volatile("st.global.cs.b64 [%0], %1;" :: "l"(p), "l"(v) : "memory");
}

// ---------------- K1: RMSNorm + per-token lr ----------------
__global__ void k_rmsnorm(const float* __restrict__ seq,
                          const float* __restrict__ scale,
                          const float* __restrict__ Wstep) {
    int tok = blockIdx.x;
    int tid = threadIdx.x;
    int lane = tid & 31, warp = tid >> 5;
    __shared__ float red[4];
    __shared__ float redp[4][4];

    float4 v = ((const float4*)(seq + (size_t)tok * DIMD))[tid];
    float ss = v.x*v.x + v.y*v.y + v.z*v.z + v.w*v.w;
#pragma unroll
    for (int o = 16; o; o >>= 1) ss += __shfl_xor_sync(0xffffffffu, ss, o);
    if (lane == 0) red[warp] = ss;
    __syncthreads();
    float tot = red[0] + red[1] + red[2] + red[3];
    float inv = rsqrtf(tot * (1.f / DIMD) + EPSV);

    float4 sc = ((const float4*)scale)[tid];
    float4 xn = make_float4(v.x*inv*sc.x, v.y*inv*sc.y, v.z*inv*sc.z, v.w*inv*sc.w);
    ((float4*)(g_xnorm + (size_t)tok * DIMD))[tid] = xn;

    int d0 = tid * 4;
    float4 wa = ((const float4*)Wstep)[d0 + 0];
    float4 wb = ((const float4*)Wstep)[d0 + 1];
    float4 wc = ((const float4*)Wstep)[d0 + 2];
    float4 wd = ((const float4*)Wstep)[d0 + 3];
    float p0 = xn.x*wa.x + xn.y*wb.x + xn.z*wc.x + xn.w*wd.x;
    float p1 = xn.x*wa.y + xn.y*wb.y + xn.z*wc.y + xn.w*wd.y;
    float p2 = xn.x*wa.z + xn.y*wb.z + xn.z*wc.z + xn.w*wd.z;
    float p3 = xn.x*wa.w + xn.y*wb.w + xn.z*wc.w + xn.w*wd.w;
#pragma unroll
    for (int o = 16; o; o >>= 1) {
        p0 += __shfl_xor_sync(0xffffffffu, p0, o);
        p1 += __shfl_xor_sync(0xffffffffu, p1, o);
        p2 += __shfl_xor_sync(0xffffffffu, p2, o);
        p3 += __shfl_xor_sync(0xffffffffu, p3, o);
    }
    if (lane == 0) { redp[warp][0] = p0; redp[warp][1] = p1; redp[warp][2] = p2; redp[warp][3] = p3; }
    __syncthreads();
    if (tid < 4) {
        float p = redp[0][tid] + redp[1][tid] + redp[2][tid] + redp[3][tid];
        float lrv = MAX_LR * sigf(p);
        int b = tok / SS, s = tok % SS;
        int t = s / CHUNK, c = s % CHUNK;
        g_lr[(((b * HEADS + tid) * NCHUNK + t) * CHUNK) + c] = lrv;
    }
}

// ---------------- K2: chunk means -> mom/dec ----------------
__global__ void k_chunkstats(const float* __restrict__ Wmom,
                             const float* __restrict__ Wdec) {
    int blk = blockIdx.x;
    int b = blk / NCHUNK, t = blk % NCHUNK;
    int tid = threadIdx.x;
    int lane = tid & 31, warp = tid >> 5;
    __shared__ float redp[4][8];

    int d0 = tid * 4;
    const float* xb = g_xnorm + ((size_t)(b * SS + t * CHUNK)) * DIMD;
    float4 m = make_float4(0.f, 0.f, 0.f, 0.f);
#pragma unroll
    for (int c = 0; c < CHUNK; c++) {
        float4 v = *(const float4*)(xb + (size_t)c * DIMD + d0);
        m.x += v.x; m.y += v.y; m.z += v.z; m.w += v.w;
    }
    m.x *= (1.f/CHUNK); m.y *= (1.f/CHUNK); m.z *= (1.f/CHUNK); m.w *= (1.f/CHUNK);

    float4 ma = ((const float4*)Wmom)[d0 + 0];
    float4 mb = ((const float4*)Wmom)[d0 + 1];
    float4 mc = ((const float4*)Wmom)[d0 + 2];
    float4 md = ((const float4*)Wmom)[d0 + 3];
    float4 da = ((const float4*)Wdec)[d0 + 0];
    float4 db = ((const float4*)Wdec)[d0 + 1];
    float4 dc = ((const float4*)Wdec)[d0 + 2];
    float4 dd = ((const float4*)Wdec)[d0 + 3];

    float p[8];
    p[0] = m.x*ma.x + m.y*mb.x + m.z*mc.x + m.w*md.x;
    p[1] = m.x*ma.y + m.y*mb.y + m.z*mc.y + m.w*md.y;
    p[2] = m.x*ma.z + m.y*mb.z + m.z*mc.z + m.w*md.z;
    p[3] = m.x*ma.w + m.y*mb.w + m.z*mc.w + m.w*md.w;
    p[4] = m.x*da.x + m.y*db.x + m.z*dc.x + m.w*dd.x;
    p[5] = m.x*da.y + m.y*db.y + m.z*dc.y + m.w*dd.y;
    p[6] = m.x*da.z + m.y*db.z + m.z*dc.z + m.w*dd.z;
    p[7] = m.x*da.w + m.y*db.w + m.z*dc.w + m.w*dd.w;
#pragma unroll
    for (int i = 0; i < 8; i++) {
#pragma unroll
        for (int o = 16; o; o >>= 1) p[i] += __shfl_xor_sync(0xffffffffu, p[i], o);
    }
    if (lane == 0) {
#pragma unroll
        for (int i = 0; i < 8; i++) redp[warp][i] = p[i];
    }
    __syncthreads();
    if (tid < 8) {
        float s = redp[0][tid] + redp[1][tid] + redp[2][tid] + redp[3][tid];
        float sv = sigf(s);
        int h = tid & 3;
        if (tid < 4) g_mom[(b * HEADS + h) * NCHUNK + t] = sv;
        else         g_dec[(b * HEADS + h) * NCHUNK + t] = sv;
    }
}

// ---------------- K3: kv projection (32-token tiles) ----------------
#define KV_ROWS 32
__global__ void __launch_bounds__(256, 2) k_kvproj(const float* __restrict__ Wkv) {
    extern __shared__ float xs[];   // 64 KB
    int rg  = blockIdx.x & 127;
    int cgp = blockIdx.x >> 7;
    int tid = threadIdx.x;

    const float4* src = (const float4*)(g_xnorm + (size_t)rg * KV_ROWS * DIMD);
#pragma unroll
    for (int i = tid; i < KV_ROWS * DIMD / 4; i += 256) ((float4*)xs)[i] = src[i];
    __syncthreads();

    int rs = tid >> 6;
    int cg = tid & 63;
    int r0 = rs * 8;
    int col = cgp * 256 + cg * 4;

    unsigned long long acc[8][2];
#pragma unroll
    for (int r = 0; r < 8; r++) { acc[r][0] = 0ull; acc[r][1] = 0ull; }

    const float* wbase = Wkv + col;
#pragma unroll 2
    for (int dt = 0; dt < DIMD; dt += 4) {
        float4 xv[8];
#pragma unroll
        for (int r = 0; r < 8; r++) xv[r] = *(const float4*)&xs[(r0 + r) * DIMD + dt];
#pragma unroll
        for (int dd = 0; dd < 4; dd++) {
            ulonglong2 wl = *(const ulonglong2*)(wbase + (size_t)(dt + dd) * 1024);
#pragma unroll
            for (int r = 0; r < 8; r++) {
                float xc = (dd == 0) ? xv[r].x : (dd == 1) ? xv[r].y : (dd == 2) ? xv[r].z : xv[r].w;
                unsigned long long kk = dup2(xc);
                acc[r][0] = fma2(kk, wl.x, acc[r][0]);
                acc[r][1] = fma2(kk, wl.y, acc[r][1]);
            }
        }
    }

    int isv = (col >= 512);
    int c2 = col - isv * 512;
    int h = c2 >> 7, j = c2 & 127;
    float* base = (isv ? g_v : g_k);
#pragma unroll
    for (int r = 0; r < 8; r++) {
        int tg = rg * KV_ROWS + r0 + r;
        int b = tg >> 11, s = tg & 2047;
        float* dst = base + ((size_t)((b * HEADS + h) * SS + s)) * DH + j;
        *(ulonglong2*)dst = make_ulonglong2(acc[r][0], acc[r][1]);
    }
}

// ---------------- K4a: per-chunk gradients (512 thr, 4x4 tiles) ----------------
#define CPG 4
#define MROWS 64
#define WPITCH 140

__device__ __forceinline__ void gemm64(const float* __restrict__ A,
                                       const float* __restrict__ W,
                                       int c0, int j0,
                                       unsigned long long acc[4][2]) {
#pragma unroll
    for (int i = 0; i < 4; i++) { acc[i][0] = 0ull; acc[i][1] = 0ull; }
#pragma unroll 2
    for (int dq = 0; dq < DH; dq += 4) {
        float4 ar[4];
#pragma unroll
        for (int i = 0; i < 4; i++) ar[i] = *(const float4*)&A[(c0 + i) * DH + dq];
#pragma unroll
        for (int dd = 0; dd < 4; dd++) {
            ulonglong2 w = *(const ulonglong2*)&W[(dq + dd) * WPITCH + j0];
#pragma unroll
            for (int i = 0; i < 4; i++) {
                float av = (dd == 0) ? ar[i].x : (dd == 1) ? ar[i].y : (dd == 2) ? ar[i].z : ar[i].w;
                unsigned long long aa = dup2(av);
                acc[i][0] = fma2(aa, w.x, acc[i][0]);
                acc[i][1] = fma2(aa, w.y, acc[i][1]);
            }
        }
    }
}

__global__ void __launch_bounds__(512, 1)
k_grad(const float* __restrict__ w0g_all, const float* __restrict__ w1g_all) {
    extern __shared__ float sm[];
    float* ws  = sm;
    float* ks  = ws + 128 * WPITCH;
    float* vs  = ks + MROWS * DH;
    float* as_ = vs + MROWS * DH;
    float* ss  = as_ + MROWS * DH;
    float* lrs = ss + MROWS * DH;

    int bh = blockIdx.x >> 5;
    int tg = blockIdx.x & 31;
    int t0 = tg * CPG;
    int tid = threadIdx.x;

    size_t rowbase = ((size_t)(bh * NCHUNK + t0)) * (CHUNK * DH);

    const float4* kg = (const float4*)(g_k + rowbase);
    const float4* vg = (const float4*)(g_v + rowbase);
    for (int i = tid; i < MROWS * DH / 4; i += 512) {
        ((float4*)ks)[i] = kg[i];
        ((float4*)vs)[i] = vg[i];
    }
    if (tid < MROWS) lrs[tid] = g_lr[(bh * NCHUNK + t0) * CHUNK + tid];
    const float4* w0g4 = (const float4*)(w0g_all + (size_t)bh * DH2);
    for (int i = tid; i < 4096; i += 512) {
        int row = i >> 5, col = (i & 31) * 4;
        *(float4*)&ws[row * WPITCH + col] = w0g4[i];
    }
    __syncthreads();

    int ty = tid >> 5, tx = tid & 31;
    int c0 = ty * 4, j0 = tx * 4;
    unsigned long long acc[4][2];

    // GEMM A
    gemm64(ks, ws, c0, j0, acc);
#pragma unroll
    for (int i = 0; i < 4; i++) {
        float2 h01 = unpk2(acc[i][0]), h23 = unpk2(acc[i][1]);
        float s0 = sigf(h01.x), s1 = sigf(h01.y), s2 = sigf(h23.x), s3 = sigf(h23.y);
        float4 av = make_float4(h01.x * s0, h01.y * s1, h23.x * s2, h23.y * s3);
        *(float4*)&ss[(c0 + i) * DH + j0]  = make_float4(s0, s1, s2, s3);
        *(float4*)&as_[(c0 + i) * DH + j0] = av;
        *(float4*)&g_a[rowbase + (size_t)(c0 + i) * DH + j0] = av;
    }
    __syncthreads();

    const float4* w1g4 = (const float4*)(w1g_all + (size_t)bh * DH2);
    for (int i = tid; i < 4096; i += 512) {
        int row = i >> 5, col = (i & 31) * 4;
        *(float4*)&ws[row * WPITCH + col] = w1g4[i];
    }
    __syncthreads();

    // GEMM B
    gemm64(as_, ws, c0, j0, acc);
#pragma unroll
    for (int i = 0; i < 4; i++) {
        float f = 2.f * lrs[c0 + i] * (1.f / DH);
        float2 p01 = unpk2(acc[i][0]), p23 = unpk2(acc[i][1]);
        float4 vv = *(const float4*)&vs[(c0 + i) * DH + j0];
        float4 Gn = make_float4(f * (vv.x - p01.x), f * (vv.y - p01.y),
                                f * (vv.z - p23.x), f * (vv.w - p23.y));
        *(float4*)&vs[(c0 + i) * DH + j0] = Gn;
        *(float4*)&g_gn[rowbase + (size_t)(c0 + i) * DH + j0] = Gn;
    }
    __syncthreads();

    {
        const float* w1g = w1g_all + (size_t)bh * DH2;
        for (int i = tid; i < DH2; i += 512) {
            ws[(i & 127) * WPITCH + (i >> 7)] = w1g[i];
        }
    }
    __syncthreads();

    // GEMM C
    gemm64(vs, ws, c0, j0, acc);
#pragma unroll
    for (int i = 0; i < 4; i++) {
        float2 d01 = unpk2(acc[i][0]), d23 = unpk2(acc[i][1]);
        float4 sv = *(const float4*)&ss[(c0 + i) * DH + j0];
        float4 av = *(const float4*)&as_[(c0 + i) * DH + j0];
        d01.x *= sv.x + av.x * (1.f - sv.x);
        d01.y *= sv.y + av.y * (1.f - sv.y);
        d23.x *= sv.z + av.z * (1.f - sv.z);
        d23.y *= sv.w + av.w * (1.f - sv.w);
        *(float4*)&g_dh[rowbase + (size_t)(c0 + i) * DH + j0] =
            make_float4(d01.x, d01.y, d23.x, d23.y);
    }
}

// ---------------- K4b: fused outer-product + momentum/decay scan (v2) ----------------
// grid 256: cid = blk>>4 (sel*8+bh), tile = blk&15 (4x4 of 32x32). block 128.
// 2 t's per sync; 4-slot ring buffer; streaming stores.
__global__ void __launch_bounds__(128) k_outer_scan(float* __restrict__ out) {
    __shared__ float As[4][CHUNK * 32];
    __shared__ float Gs[4][CHUNK * 32];
    __shared__ float moms[NCHUNK], decs[NCHUNK];

    int cid  = blockIdx.x >> 4;
    int sel  = cid >> 3, bh = cid & 7;
    int tile = blockIdx.x & 15;
    int d1b  = (tile >> 2) * 32;
    int d2b  = (tile & 3) * 32;
    int tid  = threadIdx.x;

    moms[tid] = g_mom[bh * NCHUNK + tid];
    decs[tid] = 1.f - g_dec[bh * NCHUNK + tid];

    const float* Asrc = sel ? g_a  : g_k;
    const float* Gsrc = sel ? g_gn : g_dh;
    size_t bhrow = (size_t)bh * (NCHUNK * CHUNK);

    int ld_c = tid >> 3, ld_i = (tid & 7) * 4;   // 16 rows x 32 cols, 1 float4/thread

    // prologue: stage t=0,1 into slots 0,1
#pragma unroll
    for (int s = 0; s < 2; s++) {
        *(float4*)&As[s][ld_c * 32 + ld_i] =
            *(const float4*)(Asrc + (bhrow + (size_t)s * CHUNK + ld_c) * DH + d1b + ld_i);
        *(float4*)&Gs[s][ld_c * 32 + ld_i] =
            *(const float4*)(Gsrc + (bhrow + (size_t)s * CHUNK + ld_c) * DH + d2b + ld_i);
    }
    __syncthreads();

    int w = tid >> 5, l = tid & 31;
    int rg = l >> 4, cp = l & 15;
    int r0 = w * 8 + rg * 4;

    unsigned long long m[4], u[4];
#pragma unroll
    for (int r = 0; r < 4; r++) { m[r] = 0ull; u[r] = 0ull; }

    size_t outchain = (size_t)(sel * BH + bh) * NCHUNK;

    for (int it = 0; it < NCHUNK / 2; it++) {
        int t0 = 2 * it;
        bool havenext = (it + 1 < NCHUNK / 2);
        float4 a_pre[2], g_pre[2];
        if (havenext) {
#pragma unroll
            for (int s = 0; s < 2; s++) {
                a_pre[s] = *(const float4*)(Asrc + (bhrow + (size_t)(t0 + 2 + s) * CHUNK + ld_c) * DH + d1b + ld_i);
                g_pre[s] = *(const float4*)(Gsrc + (bhrow + (size_t)(t0 + 2 + s) * CHUNK + ld_c) * DH + d2b + ld_i);
            }
        }

#pragma unroll
        for (int s = 0; s < 2; s++) {
            int t = t0 + s;
            int slot = t & 3;
            unsigned long long acc[4];
#pragma unroll
            for (int r = 0; r < 4; r++) acc[r] = 0ull;
#pragma unroll
            for (int c = 0; c < CHUNK; c++) {
                float4 av = *(const float4*)&As[slot][c * 32 + r0];
                unsigned long long g2 = *(const unsigned long long*)&Gs[slot][c * 32 + cp * 2];
                acc[0] = fma2(dup2(av.x), g2, acc[0]);
                acc[1] = fma2(dup2(av.y), g2, acc[1]);
                acc[2] = fma2(dup2(av.z), g2, acc[2]);
                acc[3] = fma2(dup2(av.w), g2, acc[3]);
            }
            unsigned long long mo = dup2(moms[t]);
            unsigned long long de = dup2(decs[t]);
            float* op = out + (outchain + t) * DH2 + (size_t)(d1b + r0) * DH + d2b + cp * 2;
#pragma unroll
            for (int r = 0; r < 4; r++) {
                m[r] = fma2(mo, m[r], acc[r]);
                u[r] = fma2(de, u[r], m[r]);
                st_cs_u64(op + (size_t)r * DH, u[r]);
            }
        }

        if (havenext) {
#pragma unroll
            for (int s = 0; s < 2; s++) {
                int slot = (t0 + 2 + s) & 3;
                *(float4*)&As[slot][ld_c * 32 + ld_i] = a_pre[s];
                *(float4*)&Gs[slot][ld_c * 32 + ld_i] = g_pre[s];
            }
        }
        __syncthreads();
    }
}

// ---------------- launch ----------------
extern "C" void kernel_launch(void* const* d_in, const int* in_sizes, int n_in,
                              void* d_out, int out_size) {
    const float* seq   = (const float*)d_in[0];
    const float* scale = (const float*)d_in[1];
    const float* Wkv   = (const float*)d_in[2];
    const float* Wstep = (const float*)d_in[3];
    const float* Wmom  = (const float*)d_in[4];
    const float* Wdec  = (const float*)d_in[5];
    const float* w0    = (const float*)d_in[6];
    const float* w1    = (const float*)d_in[7];
    float* out = (float*)d_out;

    const int GRAD_SMEM = (128 * WPITCH + 4 * MROWS * DH + 64) * 4;  // ~203 KB
    const int KV_SMEM = KV_ROWS * DIMD * 4;                           // 64 KB
    cudaFuncSetAttribute(k_grad, cudaFuncAttributeMaxDynamicSharedMemorySize, GRAD_SMEM);
    cudaFuncSetAttribute(k_kvproj, cudaFuncAttributeMaxDynamicSharedMemorySize, KV_SMEM);

    k_rmsnorm<<<BB * SS, 128>>>(seq, scale, Wstep);
    k_chunkstats<<<BB * NCHUNK, 128>>>(Wmom, Wdec);
    k_kvproj<<<512, 256, KV_SMEM>>>(Wkv);
    k_grad<<<BH * (NCHUNK / CPG), 512, GRAD_SMEM>>>(w0, w1);
    k_outer_scan<<<256, 128>>>(out);
}